// round 1
// baseline (speedup 1.0000x reference)
#include <cuda_runtime.h>
#include <cuda_bf16.h>

// DWTLoss: single-level Haar DWT L1 loss between pred and target.
// Shapes: [32,3,512,512] fp32 each. Pure streaming reduction -> HBM-bound.
//
// Per 2x2 block with diffs da,db,dc,dd (pred-target):
//   sum of 4 subband |.| contributions (incl. 0.5 normalization) =
//   max(|da+db|,|dc+dd|) + max(|da-db|,|dc-dd|)
// Total loss = (1/N) * sum over all blocks, N = 32*3*256*256 = 6291456.

#define TOTAL_FLOATS (32 * 3 * 512 * 512)        // 25,165,824
#define N_BLOCKS_HAAR (32 * 3 * 256 * 256)       // 6,291,456
#define N_ITEMS (TOTAL_FLOATS / 8)               // 3,145,728 (2 blocks per item)
#define PLANE_F4 (512 * 512 / 4)                 // 65536 float4 per plane
#define ROW_F4 (512 / 4)                         // 128 float4 per row

__device__ double g_dwt_acc;

__global__ void dwt_zero_kernel() {
    if (threadIdx.x == 0 && blockIdx.x == 0) g_dwt_acc = 0.0;
}

__global__ void __launch_bounds__(256) dwt_loss_kernel(
    const float* __restrict__ pred,
    const float* __restrict__ target)
{
    const float4* __restrict__ p4 = (const float4*)pred;
    const float4* __restrict__ t4 = (const float4*)target;

    float acc = 0.0f;
    const int stride = gridDim.x * blockDim.x;
    for (int i = blockIdx.x * blockDim.x + threadIdx.x; i < N_ITEMS; i += stride) {
        // i -> (plane, row-pair r2, col4)
        int plane = i >> 15;          // / (256*128)
        int rem   = i & 32767;
        int r2    = rem >> 7;         // / 128
        int c4    = rem & 127;
        // float4 index of row 2*r2: plane*65536 + (2*r2)*128 + c4
        int base = plane * PLANE_F4 + r2 * (2 * ROW_F4) + c4;

        float4 p0 = p4[base];
        float4 p1 = p4[base + ROW_F4];
        float4 q0 = t4[base];
        float4 q1 = t4[base + ROW_F4];

        // block 0 (cols x,y)
        float da = p0.x - q0.x, db = p0.y - q0.y;
        float dc = p1.x - q1.x, dd = p1.y - q1.y;
        float u = da + db, v = dc + dd;
        float w = da - db, x = dc - dd;
        acc += fmaxf(fabsf(u), fabsf(v)) + fmaxf(fabsf(w), fabsf(x));

        // block 1 (cols z,w)
        da = p0.z - q0.z; db = p0.w - q0.w;
        dc = p1.z - q1.z; dd = p1.w - q1.w;
        u = da + db; v = dc + dd;
        w = da - db; x = dc - dd;
        acc += fmaxf(fabsf(u), fabsf(v)) + fmaxf(fabsf(w), fabsf(x));
    }

    // intra-warp reduce
    #pragma unroll
    for (int o = 16; o > 0; o >>= 1)
        acc += __shfl_xor_sync(0xffffffffu, acc, o);

    __shared__ float sm[8];
    int lane = threadIdx.x & 31;
    int warp = threadIdx.x >> 5;
    if (lane == 0) sm[warp] = acc;
    __syncthreads();

    if (warp == 0) {
        float v = (lane < 8) ? sm[lane] : 0.0f;
        #pragma unroll
        for (int o = 4; o > 0; o >>= 1)
            v += __shfl_xor_sync(0xffffffffu, v, o);
        if (lane == 0)
            atomicAdd(&g_dwt_acc, (double)v);
    }
}

__global__ void dwt_finalize_kernel(float* __restrict__ out) {
    if (threadIdx.x == 0 && blockIdx.x == 0)
        out[0] = (float)(g_dwt_acc * (1.0 / (double)N_BLOCKS_HAAR));
}

extern "C" void kernel_launch(void* const* d_in, const int* in_sizes, int n_in,
                              void* d_out, int out_size) {
    const float* pred   = (const float*)d_in[0];
    const float* target = (const float*)d_in[1];
    float* out = (float*)d_out;

    dwt_zero_kernel<<<1, 32>>>();
    // 148 SMs * 16 CTAs/SM = 2368 CTAs, 256 threads, grid-stride
    dwt_loss_kernel<<<2368, 256>>>(pred, target);
    dwt_finalize_kernel<<<1, 32>>>(out);
}

// round 5
// speedup vs baseline: 1.0354x; 1.0354x over previous
#include <cuda_runtime.h>
#include <cuda_bf16.h>

// DWTLoss: single-level Haar DWT L1 loss between pred and target.
// [32,3,512,512] fp32 x2 = 201.3 MB streamed once -> HBM-bound.
//
// Per 2x2 block with diffs da,db,dc,dd:
//   sum of 4 normalized subband |.| terms = max(|da+db|,|dc+dd|) + max(|da-db|,|dc-dd|)
// loss = (1/N_BLOCKS) * sum, N_BLOCKS = 32*3*256*256.
//
// Single fused kernel: grid reduction via atomic double + last-CTA finalize
// that also resets state (graph-replay safe; __device__ globals start at 0).

#define N_BLOCKS_HAAR (32 * 3 * 256 * 256)   // 6,291,456
#define N_ITEMS       (32 * 3 * 256 * 128)   // 3,145,728 float4-pair items
#define GRID_CTAS     2048
#define CTA_THREADS   256
#define N_THREADS     (GRID_CTAS * CTA_THREADS)   // 524,288
#define ITEMS_PER_THR (N_ITEMS / N_THREADS)       // exactly 6
#define ROW_F4        128                          // float4 per 512-wide row

__device__ double g_dwt_acc;
__device__ unsigned int g_dwt_count;

__global__ void __launch_bounds__(CTA_THREADS) dwt_loss_fused_kernel(
    const float* __restrict__ pred,
    const float* __restrict__ target,
    float* __restrict__ out)
{
    const float4* __restrict__ p4 = (const float4*)pred;
    const float4* __restrict__ t4 = (const float4*)target;

    const int tid = blockIdx.x * CTA_THREADS + threadIdx.x;

    float acc = 0.0f;
    #pragma unroll 2
    for (int it = 0; it < ITEMS_PER_THR; it++) {
        const int i = tid + it * N_THREADS;
        // item i = (plane, row-pair, col4); float4 index of top row:
        //   base = i + (i & ~127)   (absorbs plane*2 and row-pair*2 doubling)
        const int base = i + (i & ~127);

        float4 p0 = p4[base];
        float4 p1 = p4[base + ROW_F4];
        float4 q0 = t4[base];
        float4 q1 = t4[base + ROW_F4];

        // block 0 (lanes x,y)
        float da = p0.x - q0.x, db = p0.y - q0.y;
        float dc = p1.x - q1.x, dd = p1.y - q1.y;
        acc += fmaxf(fabsf(da + db), fabsf(dc + dd))
             + fmaxf(fabsf(da - db), fabsf(dc - dd));

        // block 1 (lanes z,w)
        da = p0.z - q0.z; db = p0.w - q0.w;
        dc = p1.z - q1.z; dd = p1.w - q1.w;
        acc += fmaxf(fabsf(da + db), fabsf(dc + dd))
             + fmaxf(fabsf(da - db), fabsf(dc - dd));
    }

    // intra-warp reduce
    #pragma unroll
    for (int o = 16; o > 0; o >>= 1)
        acc += __shfl_xor_sync(0xffffffffu, acc, o);

    __shared__ float sm[CTA_THREADS / 32];
    const int lane = threadIdx.x & 31;
    const int warp = threadIdx.x >> 5;
    if (lane == 0) sm[warp] = acc;
    __syncthreads();

    if (warp == 0) {
        float v = (lane < CTA_THREADS / 32) ? sm[lane] : 0.0f;
        #pragma unroll
        for (int o = 4; o > 0; o >>= 1)
            v += __shfl_xor_sync(0xffffffffu, v, o);

        if (lane == 0) {
            atomicAdd(&g_dwt_acc, (double)v);
            __threadfence();
            unsigned int prev = atomicAdd(&g_dwt_count, 1u);
            if (prev == GRID_CTAS - 1) {
                // last CTA: all g_dwt_acc adds are visible (fence + atomic order).
                // Read-and-reset so every graph replay starts from zeroed state.
                unsigned long long raw =
                    atomicExch((unsigned long long*)&g_dwt_acc, 0ull);
                double total = __longlong_as_double((long long)raw);
                out[0] = (float)(total * (1.0 / (double)N_BLOCKS_HAAR));
                atomicExch(&g_dwt_count, 0u);
            }
        }
    }
}

extern "C" void kernel_launch(void* const* d_in, const int* in_sizes, int n_in,
                              void* d_out, int out_size) {
    const float* pred   = (const float*)d_in[0];
    const float* target = (const float*)d_in[1];
    float* out = (float*)d_out;

    dwt_loss_fused_kernel<<<GRID_CTAS, CTA_THREADS>>>(pred, target, out);
}